// round 1
// baseline (speedup 1.0000x reference)
#include <cuda_runtime.h>
#include <math.h>

#define NN 1024           // N = N_ = 1024 training/test points
#define LLt 4             // l = 4 tasks
#define DD 8              // input dim
#define NB 64             // cholesky/trsm block size
#define NSTEP 16          // NN / NB
#define LDZ 1040          // padded leading dim for Z (1025 used cols)
#define NRHS 1025         // 1024 Cx columns + 1 ytil column

// ---------------- device scratch (static: no allocation allowed) ----------------
__device__ float g_C[NN * NN];          // rbf(X, X)
__device__ float g_Cx[NN * NN];         // rbf(X, test_X)
__device__ float g_Ctt[NN * NN];        // rbf(test_X, test_X)
__device__ float g_Lf[LLt][NN * NN];    // per-batch A_i = s_i*C + I -> Cholesky L_i in-place
__device__ float g_Z[LLt][NN * LDZ];    // per-batch RHS [Cx | ytil_i] -> solved in place
__device__ float g_W[LLt][NN * NN];     // W_i = Cx^T M_i Cx
__device__ float g_Ytil[NN * LLt];      // Y @ (D^{-1/2} U)
__device__ float g_H[NN * LLt];         // [z_1..z_4] @ G
__device__ float g_Fm[NN * LLt];        // fmean matrix (N_ x l)

struct Small {
    float s[LLt];          // eigenvalues of B'
    float G[LLt][LLt];     // G[i][q] = (U^T D^{-1/2} B)[i][q]
    float B[LLt][LLt];     // task_K
    float dn[LLt];         // exp(log_noise)
    float DU[LLt][LLt];    // DU[p][i] = dns[p]*U[p][i]
    float inv2ls2;         // 0.5 / ls^2
};
__device__ Small g_sm;

// ---------------- small setup: task matrix, 4x4 Jacobi eig ----------------
__global__ void small_setup(const float* __restrict__ log_noise,
                            const float* __restrict__ covar_factor,
                            const float* __restrict__ log_var,
                            const float* __restrict__ log_ls, int rank)
{
    if (threadIdx.x != 0 || blockIdx.x != 0) return;
    double dn[LLt], dns[LLt];
    for (int p = 0; p < LLt; p++) {
        dn[p]  = exp((double)log_noise[p]);
        dns[p] = exp(-0.5 * (double)log_noise[p]);
    }
    double B[LLt][LLt];
    for (int q = 0; q < LLt; q++)
        for (int r = 0; r < LLt; r++) {
            double s = 0.0;
            for (int k = 0; k < rank; k++)
                s += (double)covar_factor[q * rank + k] * (double)covar_factor[r * rank + k];
            if (q == r) s += exp((double)log_var[q]);
            B[q][r] = s;
        }
    // B' = D^{-1/2} B D^{-1/2}, Jacobi eigendecomposition B' = V diag(s) V^T
    double A[LLt][LLt], V[LLt][LLt];
    for (int q = 0; q < LLt; q++)
        for (int r = 0; r < LLt; r++) {
            A[q][r] = dns[q] * B[q][r] * dns[r];
            V[q][r] = (q == r) ? 1.0 : 0.0;
        }
    for (int sweep = 0; sweep < 40; sweep++) {
        for (int p = 0; p < LLt - 1; p++)
            for (int q = p + 1; q < LLt; q++) {
                double apq = A[p][q];
                if (fabs(apq) < 1e-300) continue;
                double theta = 0.5 * atan2(2.0 * apq, A[q][q] - A[p][p]);
                double c = cos(theta), s = sin(theta);
                for (int k = 0; k < LLt; k++) {
                    double akp = A[k][p], akq = A[k][q];
                    A[k][p] = c * akp - s * akq;
                    A[k][q] = s * akp + c * akq;
                }
                for (int k = 0; k < LLt; k++) {
                    double apk = A[p][k], aqk = A[q][k];
                    A[p][k] = c * apk - s * aqk;
                    A[q][k] = s * apk + c * aqk;
                }
                for (int k = 0; k < LLt; k++) {
                    double vkp = V[k][p], vkq = V[k][q];
                    V[k][p] = c * vkp - s * vkq;
                    V[k][q] = s * vkp + c * vkq;
                }
            }
    }
    for (int i = 0; i < LLt; i++) g_sm.s[i] = (float)A[i][i];
    for (int p = 0; p < LLt; p++)
        for (int i = 0; i < LLt; i++)
            g_sm.DU[p][i] = (float)(dns[p] * V[p][i]);
    for (int i = 0; i < LLt; i++)
        for (int q = 0; q < LLt; q++) {
            double s = 0.0;
            for (int p = 0; p < LLt; p++) s += V[p][i] * dns[p] * B[p][q];
            g_sm.G[i][q] = (float)s;
        }
    for (int q = 0; q < LLt; q++)
        for (int r = 0; r < LLt; r++) g_sm.B[q][r] = (float)B[q][r];
    for (int p = 0; p < LLt; p++) g_sm.dn[p] = (float)dn[p];
    g_sm.inv2ls2 = (float)(0.5 * exp(-2.0 * (double)log_ls[0]));
}

// ---------------- Ytil = Y @ DU ----------------
__global__ void ytil_kernel(const float* __restrict__ Y)
{
    int n = blockIdx.x * 256 + threadIdx.x;
    if (n >= NN) return;
    float y0 = Y[n * 4 + 0], y1 = Y[n * 4 + 1], y2 = Y[n * 4 + 2], y3 = Y[n * 4 + 3];
    #pragma unroll
    for (int i = 0; i < LLt; i++)
        g_Ytil[n * 4 + i] = y0 * g_sm.DU[0][i] + y1 * g_sm.DU[1][i]
                          + y2 * g_sm.DU[2][i] + y3 * g_sm.DU[3][i];
}

// ---------------- RBF kernel matrices ----------------
__global__ void rbf_kernel(const float* __restrict__ X1, const float* __restrict__ X2,
                           float* __restrict__ out, int n1, int n2)
{
    int idx = blockIdx.x * 256 + threadIdx.x;
    if (idx >= n1 * n2) return;
    int i = idx / n2, j = idx - i * n2;
    float d2 = 0.f;
    #pragma unroll
    for (int d = 0; d < DD; d++) {
        float t = X1[i * DD + d] - X2[j * DD + d];
        d2 += t * t;
    }
    out[idx] = expf(-d2 * g_sm.inv2ls2);
}

// ---------------- A_i = s_i * C + I ----------------
__global__ void buildA_kernel()
{
    int e = blockIdx.x * 256 + threadIdx.x;
    int b = blockIdx.z;
    if (e >= NN * NN) return;
    int n = e >> 10, m = e & 1023;
    g_Lf[b][e] = g_sm.s[b] * g_C[e] + (n == m ? 1.f : 0.f);
}

// ---------------- Z = [Cx | ytil_b] ----------------
__global__ void init_Z()
{
    int n = blockIdx.x;
    int b = blockIdx.y;
    float* Zr = &g_Z[b][(long)n * LDZ];
    const float* Cr = &g_Cx[(long)n * NN];
    for (int c = threadIdx.x; c < NN; c += 256) Zr[c] = Cr[c];
    if (threadIdx.x == 0) Zr[NN] = g_Ytil[n * 4 + b];
}

// ---------------- batched blocked Cholesky: diag block factor ----------------
__global__ void potf2_kernel(int k)
{
    int b = blockIdx.x;
    int t = threadIdx.x;      // 64 threads
    __shared__ float sA[64][65];
    float* Lb = g_Lf[b];
    int off = k * NB;
    for (int r = 0; r < 64; r++) sA[r][t] = Lb[(long)(off + r) * NN + off + t];
    __syncthreads();
    for (int j = 0; j < 64; j++) {
        if (t == j) sA[j][j] = sqrtf(sA[j][j]);
        __syncthreads();
        float inv = 1.f / sA[j][j];
        if (t > j) sA[t][j] *= inv;
        __syncthreads();
        if (t > j) {
            float ltj = sA[t][j];
            for (int c = j + 1; c <= t; c++) sA[t][c] -= ltj * sA[c][j];
        }
        __syncthreads();
    }
    for (int r = 0; r < 64; r++) Lb[(long)(off + r) * NN + off + t] = sA[r][t];
}

// ---------------- panel: L21 = A21 * L11^{-T} ----------------
__global__ void chol_panel(int k)
{
    int b = blockIdx.y;
    int t = threadIdx.x;      // 64 threads, one row each
    int rowbase = (k + 1) * NB + blockIdx.x * 64;
    __shared__ float sL[64][65];
    __shared__ float sA[64][65];
    float* Lb = g_Lf[b];
    for (int r = 0; r < 64; r++) sL[r][t] = Lb[(long)(k * NB + r) * NN + k * NB + t];
    for (int r = 0; r < 64; r++) sA[r][t] = Lb[(long)(rowbase + r) * NN + k * NB + t];
    __syncthreads();
    for (int j = 0; j < 64; j++) {
        float acc = sA[t][j];
        for (int c = 0; c < j; c++) acc -= sA[t][c] * sL[j][c];
        sA[t][j] = acc / sL[j][j];
    }
    __syncthreads();
    for (int r = 0; r < 64; r++) Lb[(long)(rowbase + r) * NN + k * NB + t] = sA[r][t];
}

// ---------------- TRSM diag solves ----------------
__global__ void trsm_fwd_diag(int k)
{
    int b = blockIdx.y;
    int t = threadIdx.x;
    int col = blockIdx.x * 64 + t;
    __shared__ float sL[64][65];
    __shared__ float sX[64][65];
    float* Lb = g_Lf[b];
    float* Zb = g_Z[b];
    for (int r = 0; r < 64; r++) sL[r][t] = Lb[(long)(k * NB + r) * NN + k * NB + t];
    bool ok = col < NRHS;
    for (int r = 0; r < 64; r++) sX[r][t] = ok ? Zb[(long)(k * NB + r) * LDZ + col] : 0.f;
    __syncthreads();
    for (int j = 0; j < 64; j++) {
        float a0 = 0.f, a1 = 0.f, a2 = 0.f, a3 = 0.f;
        int c = 0;
        for (; c + 3 < j; c += 4) {
            a0 -= sL[j][c]     * sX[c][t];
            a1 -= sL[j][c + 1] * sX[c + 1][t];
            a2 -= sL[j][c + 2] * sX[c + 2][t];
            a3 -= sL[j][c + 3] * sX[c + 3][t];
        }
        for (; c < j; c++) a0 -= sL[j][c] * sX[c][t];
        sX[j][t] = (sX[j][t] + a0 + a1 + a2 + a3) / sL[j][j];
    }
    if (ok)
        for (int r = 0; r < 64; r++) Zb[(long)(k * NB + r) * LDZ + col] = sX[r][t];
}

__global__ void trsm_bwd_diag(int k)
{
    int b = blockIdx.y;
    int t = threadIdx.x;
    int col = blockIdx.x * 64 + t;
    __shared__ float sL[64][65];
    __shared__ float sX[64][65];
    float* Lb = g_Lf[b];
    float* Zb = g_Z[b];
    for (int r = 0; r < 64; r++) sL[r][t] = Lb[(long)(k * NB + r) * NN + k * NB + t];
    bool ok = col < NRHS;
    for (int r = 0; r < 64; r++) sX[r][t] = ok ? Zb[(long)(k * NB + r) * LDZ + col] : 0.f;
    __syncthreads();
    for (int j = 63; j >= 0; j--) {
        float a0 = 0.f, a1 = 0.f, a2 = 0.f, a3 = 0.f;
        int c = j + 1;
        for (; c + 3 < 64; c += 4) {
            a0 -= sL[c][j]     * sX[c][t];
            a1 -= sL[c + 1][j] * sX[c + 1][t];
            a2 -= sL[c + 2][j] * sX[c + 2][t];
            a3 -= sL[c + 3][j] * sX[c + 3][t];
        }
        for (; c < 64; c++) a0 -= sL[c][j] * sX[c][t];
        sX[j][t] = (sX[j][t] + a0 + a1 + a2 + a3) / sL[j][j];
    }
    if (ok)
        for (int r = 0; r < 64; r++) Zb[(long)(k * NB + r) * LDZ + col] = sX[r][t];
}

// ---------------- generic batched SGEMM: C = beta*C + alpha*op(A)*op(B) ----------------
__global__ void gemm64(const float* __restrict__ A, int lda, long strA, int tA,
                       const float* __restrict__ B, int ldb, long strB, int tB,
                       float* __restrict__ C, int ldc, long strC,
                       int M, int Nq, int K, float alpha, float beta, int lowerOnly)
{
    int bi = blockIdx.x, bj = blockIdx.y, bz = blockIdx.z;
    if (lowerOnly && bj > bi) return;
    A += (long)bz * strA;
    B += (long)bz * strB;
    C += (long)bz * strC;
    __shared__ __align__(16) float As[16][68];
    __shared__ __align__(16) float Bs[16][68];
    int tid = threadIdx.x;
    int tr = tid >> 4, tc = tid & 15;
    float acc[4][4];
    #pragma unroll
    for (int u = 0; u < 4; u++)
        #pragma unroll
        for (int v = 0; v < 4; v++) acc[u][v] = 0.f;

    for (int k0 = 0; k0 < K; k0 += 16) {
        #pragma unroll
        for (int e = tid; e < 1024; e += 256) {
            int k, m;
            if (tA) { k = e >> 6; m = e & 63; } else { k = e & 15; m = e >> 4; }
            int row = bi * 64 + m;
            float v = 0.f;
            if (row < M)
                v = tA ? A[(long)(k0 + k) * lda + row] : A[(long)row * lda + (k0 + k)];
            As[k][m] = v;
        }
        #pragma unroll
        for (int e = tid; e < 1024; e += 256) {
            int k, n;
            if (tB) { k = e & 15; n = e >> 4; } else { k = e >> 6; n = e & 63; }
            int col = bj * 64 + n;
            float v = 0.f;
            if (col < Nq)
                v = tB ? B[(long)col * ldb + (k0 + k)] : B[(long)(k0 + k) * ldb + col];
            Bs[k][n] = v;
        }
        __syncthreads();
        #pragma unroll
        for (int k = 0; k < 16; k++) {
            float4 a = *reinterpret_cast<float4*>(&As[k][tr * 4]);
            float4 bb = *reinterpret_cast<float4*>(&Bs[k][tc * 4]);
            acc[0][0] += a.x * bb.x; acc[0][1] += a.x * bb.y; acc[0][2] += a.x * bb.z; acc[0][3] += a.x * bb.w;
            acc[1][0] += a.y * bb.x; acc[1][1] += a.y * bb.y; acc[1][2] += a.y * bb.z; acc[1][3] += a.y * bb.w;
            acc[2][0] += a.z * bb.x; acc[2][1] += a.z * bb.y; acc[2][2] += a.z * bb.z; acc[2][3] += a.z * bb.w;
            acc[3][0] += a.w * bb.x; acc[3][1] += a.w * bb.y; acc[3][2] += a.w * bb.z; acc[3][3] += a.w * bb.w;
        }
        __syncthreads();
    }
    #pragma unroll
    for (int u = 0; u < 4; u++) {
        int row = bi * 64 + tr * 4 + u;
        if (row >= M) continue;
        #pragma unroll
        for (int v = 0; v < 4; v++) {
            int col = bj * 64 + tc * 4 + v;
            if (col < Nq) {
                long off = (long)row * ldc + col;
                float o = alpha * acc[u][v];
                if (beta != 0.f) o += beta * C[off];
                C[off] = o;
            }
        }
    }
}

// ---------------- fmean helpers ----------------
__global__ void hk_kernel()
{
    int n = blockIdx.x * 256 + threadIdx.x;
    if (n >= NN) return;
    float z0 = g_Z[0][(long)n * LDZ + NN];
    float z1 = g_Z[1][(long)n * LDZ + NN];
    float z2 = g_Z[2][(long)n * LDZ + NN];
    float z3 = g_Z[3][(long)n * LDZ + NN];
    #pragma unroll
    for (int q = 0; q < LLt; q++)
        g_H[n * 4 + q] = z0 * g_sm.G[0][q] + z1 * g_sm.G[1][q]
                       + z2 * g_sm.G[2][q] + z3 * g_sm.G[3][q];
}

__global__ void fmean_scatter(float* __restrict__ out)
{
    int idx = blockIdx.x * 256 + threadIdx.x;
    if (idx >= NN * LLt) return;
    int m = idx >> 2, q = idx & 3;
    float v = g_Fm[m * 4 + q];
    out[(long)q * NN + m] = v;                                   // fmean (N_*l, 1)
    out[4096L + 2L * 16777216L + (long)m * 4 + q] = v;           // fmean.reshape(l,N_).T
}

// ---------------- fvar assembly ----------------
__global__ void fvar_kernel(float* __restrict__ out)
{
    int idx = blockIdx.x * 256 + threadIdx.x;   // 262144 threads
    int a  = idx >> 8;
    int b4 = idx & 255;
    long vi = (long)a * 256 + b4;
    float4 vt = reinterpret_cast<const float4*>(g_Ctt)[vi];
    float4 w0 = reinterpret_cast<const float4*>(g_W[0])[vi];
    float4 w1 = reinterpret_cast<const float4*>(g_W[1])[vi];
    float4 w2 = reinterpret_cast<const float4*>(g_W[2])[vi];
    float4 w3 = reinterpret_cast<const float4*>(g_W[3])[vi];
    float4* fv = reinterpret_cast<float4*>(out + 4096);
    #pragma unroll
    for (int q = 0; q < 4; q++) {
        #pragma unroll
        for (int r = 0; r < 4; r++) {
            float cb = g_sm.B[q][r];
            float c0 = g_sm.G[0][q] * g_sm.G[0][r];
            float c1 = g_sm.G[1][q] * g_sm.G[1][r];
            float c2 = g_sm.G[2][q] * g_sm.G[2][r];
            float c3 = g_sm.G[3][q] * g_sm.G[3][r];
            float4 v;
            v.x = cb * vt.x - c0 * w0.x - c1 * w1.x - c2 * w2.x - c3 * w3.x;
            v.y = cb * vt.y - c0 * w0.y - c1 * w1.y - c2 * w2.y - c3 * w3.y;
            v.z = cb * vt.z - c0 * w0.z - c1 * w1.z - c2 * w2.z - c3 * w3.z;
            v.w = cb * vt.w - c0 * w0.w - c1 * w1.w - c2 * w2.w - c3 * w3.w;
            fv[(long)(q * NN + a) * 1024 + r * 256 + b4] = v;
        }
    }
}

// ---------------- noise output ----------------
__global__ void noise_zero(float* __restrict__ out)
{
    long i = (long)blockIdx.x * 256 + threadIdx.x;   // 4194304 float4's
    float4 z = make_float4(0.f, 0.f, 0.f, 0.f);
    reinterpret_cast<float4*>(out + 4096 + 16777216L)[i] = z;
}

__global__ void noise_diag(float* __restrict__ out)
{
    int r = blockIdx.x * 256 + threadIdx.x;
    if (r >= 4096) return;
    out[4096 + 16777216L + (long)r * 4096 + r] = g_sm.dn[r >> 10];
}

// ---------------- launcher ----------------
extern "C" void kernel_launch(void* const* d_in, const int* in_sizes, int n_in,
                              void* d_out, int out_size)
{
    const float* X      = (const float*)d_in[0];
    const float* tX     = (const float*)d_in[1];
    const float* Y      = (const float*)d_in[2];
    const float* lnoise = (const float*)d_in[3];
    const float* cf     = (const float*)d_in[4];
    const float* lvar   = (const float*)d_in[5];
    const float* lls    = (const float*)d_in[6];
    float* out = (float*)d_out;
    int l = in_sizes[3];
    int rank = in_sizes[4] / l;

    float *C_, *Cx_, *Lf_, *Z_, *W_, *H_, *Fm_;
    cudaGetSymbolAddress((void**)&C_,  g_C);
    cudaGetSymbolAddress((void**)&Cx_, g_Cx);
    cudaGetSymbolAddress((void**)&Lf_, g_Lf);
    cudaGetSymbolAddress((void**)&Z_,  g_Z);
    cudaGetSymbolAddress((void**)&W_,  g_W);
    cudaGetSymbolAddress((void**)&H_,  g_H);
    cudaGetSymbolAddress((void**)&Fm_, g_Fm);
    float* Ctt_;
    cudaGetSymbolAddress((void**)&Ctt_, g_Ctt);

    small_setup<<<1, 32>>>(lnoise, cf, lvar, lls, rank);
    ytil_kernel<<<4, 256>>>(Y);

    int nb2 = (NN * NN + 255) / 256;
    rbf_kernel<<<nb2, 256>>>(X,  X,  C_,   NN, NN);
    rbf_kernel<<<nb2, 256>>>(X,  tX, Cx_,  NN, NN);
    rbf_kernel<<<nb2, 256>>>(tX, tX, Ctt_, NN, NN);

    buildA_kernel<<<dim3(nb2, 1, LLt), 256>>>();
    init_Z<<<dim3(NN, LLt), 256>>>();

    // batched blocked Cholesky of A_i = s_i*C + I (lower, in place)
    for (int k = 0; k < NSTEP; k++) {
        potf2_kernel<<<LLt, 64>>>(k);
        int mrem = NSTEP - 1 - k;
        if (mrem > 0) {
            chol_panel<<<dim3(mrem, LLt), 64>>>(k);
            gemm64<<<dim3(mrem, mrem, LLt), 256>>>(
                Lf_ + (long)((k + 1) * NB) * NN + k * NB, NN, (long)NN * NN, 0,
                Lf_ + (long)((k + 1) * NB) * NN + k * NB, NN, (long)NN * NN, 1,
                Lf_ + (long)((k + 1) * NB) * NN + (k + 1) * NB, NN, (long)NN * NN,
                mrem * NB, mrem * NB, NB, -1.f, 1.f, 1);
        }
    }
    // forward TRSM: L Z' = Z
    for (int k = 0; k < NSTEP; k++) {
        trsm_fwd_diag<<<dim3(17, LLt), 64>>>(k);
        int mrem = NSTEP - 1 - k;
        if (mrem > 0) {
            gemm64<<<dim3(mrem, 17, LLt), 256>>>(
                Lf_ + (long)((k + 1) * NB) * NN + k * NB, NN, (long)NN * NN, 0,
                Z_ + (long)(k * NB) * LDZ, LDZ, (long)NN * LDZ, 0,
                Z_ + (long)((k + 1) * NB) * LDZ, LDZ, (long)NN * LDZ,
                mrem * NB, NRHS, NB, -1.f, 1.f, 0);
        }
    }
    // backward TRSM: L^T Z'' = Z'
    for (int k = NSTEP - 1; k >= 0; k--) {
        trsm_bwd_diag<<<dim3(17, LLt), 64>>>(k);
        if (k > 0) {
            gemm64<<<dim3(k, 17, LLt), 256>>>(
                Lf_ + (long)(k * NB) * NN, NN, (long)NN * NN, 1,
                Z_ + (long)(k * NB) * LDZ, LDZ, (long)NN * LDZ, 0,
                Z_, LDZ, (long)NN * LDZ,
                k * NB, NRHS, NB, -1.f, 1.f, 0);
        }
    }
    // W_i = Cx^T Z_i  (batched 1024^3)
    gemm64<<<dim3(16, 16, LLt), 256>>>(
        Cx_, NN, 0L, 1,
        Z_, LDZ, (long)NN * LDZ, 0,
        W_, NN, (long)NN * NN,
        NN, NN, NN, 1.f, 0.f, 0);

    // fmean = Cx^T ([z_1..z_4] G)
    hk_kernel<<<4, 256>>>();
    gemm64<<<dim3(16, 1, 1), 256>>>(
        Cx_, NN, 0L, 1,
        H_, LLt, 0L, 0,
        Fm_, LLt, 0L,
        NN, LLt, NN, 1.f, 0.f, 0);
    fmean_scatter<<<16, 256>>>(out);

    // fvar and noise outputs
    fvar_kernel<<<1024, 256>>>(out);
    noise_zero<<<16384, 256>>>(out);
    noise_diag<<<16, 256>>>(out);
}

// round 2
// speedup vs baseline: 1.2825x; 1.2825x over previous
#include <cuda_runtime.h>
#include <math.h>

#define NN 1024           // N = N_ = 1024 training/test points
#define LLt 4             // l = 4 tasks
#define DD 8              // input dim
#define NB 64             // cholesky/trsm block size
#define NSTEP 16          // NN / NB
#define LDZ 1040          // padded leading dim for Z (1025 used cols)
#define NRHS 1025         // 1024 Cx columns + 1 ytil column

// ---------------- device scratch (static: no allocation allowed) ----------------
__device__ float g_C[NN * NN];          // rbf(X, X)
__device__ float g_Cx[NN * NN];         // rbf(X, test_X)
__device__ float g_Ctt[NN * NN];        // rbf(test_X, test_X)
__device__ float g_Lf[LLt][NN * NN];    // per-batch A_i = s_i*C + I -> Cholesky L_i in-place
__device__ float g_Z[LLt][NN * LDZ];    // per-batch RHS [Cx | ytil_i] -> T_i = L_i^{-1}[Cx|ytil]
__device__ float g_W[LLt][NN * NN];     // W_i = T_i^T T_i
__device__ float g_Ytil[NN * LLt];      // Y @ (D^{-1/2} U)
__device__ float g_Fp[LLt][NN];         // per-batch T_i^T u_i

struct Small {
    float s[LLt];          // eigenvalues of B'
    float G[LLt][LLt];     // G[i][q] = (U^T D^{-1/2} B)[i][q]
    float B[LLt][LLt];     // task_K
    float dn[LLt];         // exp(log_noise)
    float DU[LLt][LLt];    // DU[p][i] = dns[p]*U[p][i]
    float inv2ls2;         // 0.5 / ls^2
};
__device__ Small g_sm;

// ---------------- small setup: task matrix, 4x4 Jacobi eig ----------------
__global__ void small_setup(const float* __restrict__ log_noise,
                            const float* __restrict__ covar_factor,
                            const float* __restrict__ log_var,
                            const float* __restrict__ log_ls, int rank)
{
    if (threadIdx.x != 0 || blockIdx.x != 0) return;
    double dn[LLt], dns[LLt];
    for (int p = 0; p < LLt; p++) {
        dn[p]  = exp((double)log_noise[p]);
        dns[p] = exp(-0.5 * (double)log_noise[p]);
    }
    double B[LLt][LLt];
    for (int q = 0; q < LLt; q++)
        for (int r = 0; r < LLt; r++) {
            double s = 0.0;
            for (int k = 0; k < rank; k++)
                s += (double)covar_factor[q * rank + k] * (double)covar_factor[r * rank + k];
            if (q == r) s += exp((double)log_var[q]);
            B[q][r] = s;
        }
    double A[LLt][LLt], V[LLt][LLt];
    for (int q = 0; q < LLt; q++)
        for (int r = 0; r < LLt; r++) {
            A[q][r] = dns[q] * B[q][r] * dns[r];
            V[q][r] = (q == r) ? 1.0 : 0.0;
        }
    for (int sweep = 0; sweep < 40; sweep++) {
        for (int p = 0; p < LLt - 1; p++)
            for (int q = p + 1; q < LLt; q++) {
                double apq = A[p][q];
                if (fabs(apq) < 1e-300) continue;
                double theta = 0.5 * atan2(2.0 * apq, A[q][q] - A[p][p]);
                double c = cos(theta), s = sin(theta);
                for (int k = 0; k < LLt; k++) {
                    double akp = A[k][p], akq = A[k][q];
                    A[k][p] = c * akp - s * akq;
                    A[k][q] = s * akp + c * akq;
                }
                for (int k = 0; k < LLt; k++) {
                    double apk = A[p][k], aqk = A[q][k];
                    A[p][k] = c * apk - s * aqk;
                    A[q][k] = s * apk + c * aqk;
                }
                for (int k = 0; k < LLt; k++) {
                    double vkp = V[k][p], vkq = V[k][q];
                    V[k][p] = c * vkp - s * vkq;
                    V[k][q] = s * vkp + c * vkq;
                }
            }
    }
    for (int i = 0; i < LLt; i++) g_sm.s[i] = (float)A[i][i];
    for (int p = 0; p < LLt; p++)
        for (int i = 0; i < LLt; i++)
            g_sm.DU[p][i] = (float)(dns[p] * V[p][i]);
    for (int i = 0; i < LLt; i++)
        for (int q = 0; q < LLt; q++) {
            double s = 0.0;
            for (int p = 0; p < LLt; p++) s += V[p][i] * dns[p] * B[p][q];
            g_sm.G[i][q] = (float)s;
        }
    for (int q = 0; q < LLt; q++)
        for (int r = 0; r < LLt; r++) g_sm.B[q][r] = (float)B[q][r];
    for (int p = 0; p < LLt; p++) g_sm.dn[p] = (float)dn[p];
    g_sm.inv2ls2 = (float)(0.5 * exp(-2.0 * (double)log_ls[0]));
}

// ---------------- Ytil = Y @ DU ----------------
__global__ void ytil_kernel(const float* __restrict__ Y)
{
    int n = blockIdx.x * 256 + threadIdx.x;
    if (n >= NN) return;
    float y0 = Y[n * 4 + 0], y1 = Y[n * 4 + 1], y2 = Y[n * 4 + 2], y3 = Y[n * 4 + 3];
    #pragma unroll
    for (int i = 0; i < LLt; i++)
        g_Ytil[n * 4 + i] = y0 * g_sm.DU[0][i] + y1 * g_sm.DU[1][i]
                          + y2 * g_sm.DU[2][i] + y3 * g_sm.DU[3][i];
}

// ---------------- RBF kernel matrices ----------------
__global__ void rbf_kernel(const float* __restrict__ X1, const float* __restrict__ X2,
                           float* __restrict__ out, int n1, int n2)
{
    int idx = blockIdx.x * 256 + threadIdx.x;
    if (idx >= n1 * n2) return;
    int i = idx / n2, j = idx - i * n2;
    float d2 = 0.f;
    #pragma unroll
    for (int d = 0; d < DD; d++) {
        float t = X1[i * DD + d] - X2[j * DD + d];
        d2 += t * t;
    }
    out[idx] = expf(-d2 * g_sm.inv2ls2);
}

// ---------------- A_i = s_i * C + I ----------------
__global__ void buildA_kernel()
{
    int e = blockIdx.x * 256 + threadIdx.x;
    int b = blockIdx.z;
    if (e >= NN * NN) return;
    int n = e >> 10, m = e & 1023;
    g_Lf[b][e] = g_sm.s[b] * g_C[e] + (n == m ? 1.f : 0.f);
}

// ---------------- Z = [Cx | ytil_b] ----------------
__global__ void init_Z()
{
    int n = blockIdx.x;
    int b = blockIdx.y;
    float* Zr = &g_Z[b][(long)n * LDZ];
    const float* Cr = &g_Cx[(long)n * NN];
    for (int c = threadIdx.x; c < NN; c += 256) Zr[c] = Cr[c];
    if (threadIdx.x == 0) Zr[NN] = g_Ytil[n * 4 + b];
}

// ---------------- batched blocked Cholesky: diag block factor ----------------
__global__ void potf2_kernel(int k)
{
    int b = blockIdx.x;
    int t = threadIdx.x;      // 64 threads
    __shared__ float sA[64][65];
    float* Lb = g_Lf[b];
    int off = k * NB;
    for (int r = 0; r < 64; r++) sA[r][t] = Lb[(long)(off + r) * NN + off + t];
    __syncthreads();
    for (int j = 0; j < 64; j++) {
        if (t == j) sA[j][j] = sqrtf(sA[j][j]);
        __syncthreads();
        float inv = 1.f / sA[j][j];
        if (t > j) sA[t][j] *= inv;
        __syncthreads();
        if (t > j) {
            float ltj = sA[t][j];
            for (int c = j + 1; c <= t; c++) sA[t][c] -= ltj * sA[c][j];
        }
        __syncthreads();
    }
    for (int r = 0; r < 64; r++) Lb[(long)(off + r) * NN + off + t] = sA[r][t];
}

// ---------------- panel: L21 = A21 * L11^{-T} ----------------
__global__ void chol_panel(int k)
{
    int b = blockIdx.y;
    int t = threadIdx.x;      // 64 threads, one row each
    int rowbase = (k + 1) * NB + blockIdx.x * 64;
    __shared__ float sL[64][65];
    __shared__ float sA[64][65];
    float* Lb = g_Lf[b];
    for (int r = 0; r < 64; r++) sL[r][t] = Lb[(long)(k * NB + r) * NN + k * NB + t];
    for (int r = 0; r < 64; r++) sA[r][t] = Lb[(long)(rowbase + r) * NN + k * NB + t];
    __syncthreads();
    for (int j = 0; j < 64; j++) {
        float acc = sA[t][j];
        for (int c = 0; c < j; c++) acc -= sA[t][c] * sL[j][c];
        sA[t][j] = acc / sL[j][j];
    }
    __syncthreads();
    for (int r = 0; r < 64; r++) Lb[(long)(rowbase + r) * NN + k * NB + t] = sA[r][t];
}

// ---------------- forward TRSM diag solve ----------------
__global__ void trsm_fwd_diag(int k)
{
    int b = blockIdx.y;
    int t = threadIdx.x;
    int col = blockIdx.x * 64 + t;
    __shared__ float sL[64][65];
    __shared__ float sX[64][65];
    float* Lb = g_Lf[b];
    float* Zb = g_Z[b];
    for (int r = 0; r < 64; r++) sL[r][t] = Lb[(long)(k * NB + r) * NN + k * NB + t];
    bool ok = col < NRHS;
    for (int r = 0; r < 64; r++) sX[r][t] = ok ? Zb[(long)(k * NB + r) * LDZ + col] : 0.f;
    __syncthreads();
    for (int j = 0; j < 64; j++) {
        float a0 = 0.f, a1 = 0.f, a2 = 0.f, a3 = 0.f;
        int c = 0;
        for (; c + 3 < j; c += 4) {
            a0 -= sL[j][c]     * sX[c][t];
            a1 -= sL[j][c + 1] * sX[c + 1][t];
            a2 -= sL[j][c + 2] * sX[c + 2][t];
            a3 -= sL[j][c + 3] * sX[c + 3][t];
        }
        for (; c < j; c++) a0 -= sL[j][c] * sX[c][t];
        sX[j][t] = (sX[j][t] + a0 + a1 + a2 + a3) / sL[j][j];
    }
    if (ok)
        for (int r = 0; r < 64; r++) Zb[(long)(k * NB + r) * LDZ + col] = sX[r][t];
}

// ---------------- 128x128-tile SGEMM: C = beta*C + alpha*op(A)*op(B) ----------------
// 256 threads, 8x8 micro-tile per thread. sym!=0: also mirror-write C^T (syrk).
__global__ void __launch_bounds__(256, 2)
gemm128(const float* __restrict__ A, int lda, long strA, int tA,
        const float* __restrict__ B, int ldb, long strB, int tB,
        float* __restrict__ C, int ldc, long strC,
        int M, int Nq, int K, float alpha, float beta, int lowerOnly, int sym)
{
    int bi = blockIdx.x, bj = blockIdx.y, bz = blockIdx.z;
    if (lowerOnly && bj > bi) return;
    A += (long)bz * strA;
    B += (long)bz * strB;
    C += (long)bz * strC;
    __shared__ __align__(16) float As[16][132];
    __shared__ __align__(16) float Bs[16][132];
    int tid = threadIdx.x;
    int tr = tid >> 4, tc = tid & 15;
    float acc[8][8];
    #pragma unroll
    for (int u = 0; u < 8; u++)
        #pragma unroll
        for (int v = 0; v < 8; v++) acc[u][v] = 0.f;

    for (int k0 = 0; k0 < K; k0 += 16) {
        #pragma unroll
        for (int e = tid; e < 2048; e += 256) {
            int k, m;
            if (tA) { k = e >> 7; m = e & 127; } else { k = e & 15; m = e >> 4; }
            int row = bi * 128 + m;
            float v = 0.f;
            if (row < M)
                v = tA ? A[(long)(k0 + k) * lda + row] : A[(long)row * lda + (k0 + k)];
            As[k][m] = v;
        }
        #pragma unroll
        for (int e = tid; e < 2048; e += 256) {
            int k, n;
            if (tB) { k = e & 15; n = e >> 4; } else { k = e >> 7; n = e & 127; }
            int col = bj * 128 + n;
            float v = 0.f;
            if (col < Nq)
                v = tB ? B[(long)col * ldb + (k0 + k)] : B[(long)(k0 + k) * ldb + col];
            Bs[k][n] = v;
        }
        __syncthreads();
        #pragma unroll
        for (int k = 0; k < 16; k++) {
            float a[8], b[8];
            *reinterpret_cast<float4*>(&a[0]) = *reinterpret_cast<float4*>(&As[k][tr * 4]);
            *reinterpret_cast<float4*>(&a[4]) = *reinterpret_cast<float4*>(&As[k][64 + tr * 4]);
            *reinterpret_cast<float4*>(&b[0]) = *reinterpret_cast<float4*>(&Bs[k][tc * 4]);
            *reinterpret_cast<float4*>(&b[4]) = *reinterpret_cast<float4*>(&Bs[k][64 + tc * 4]);
            #pragma unroll
            for (int u = 0; u < 8; u++)
                #pragma unroll
                for (int v = 0; v < 8; v++)
                    acc[u][v] += a[u] * b[v];
        }
        __syncthreads();
    }
    #pragma unroll
    for (int u = 0; u < 8; u++) {
        int row = bi * 128 + ((u < 4) ? tr * 4 + u : 64 + tr * 4 + (u - 4));
        if (row >= M) continue;
        #pragma unroll
        for (int v = 0; v < 8; v++) {
            int col = bj * 128 + ((v < 4) ? tc * 4 + v : 64 + tc * 4 + (v - 4));
            if (col >= Nq) continue;
            long off = (long)row * ldc + col;
            float o = alpha * acc[u][v];
            if (beta != 0.f) o += beta * C[off];
            C[off] = o;
            if (sym) C[(long)col * ldc + row] = o;
        }
    }
}

// ---------------- fmean: Fp_b[m] = sum_n T_b[n][m] * u_b[n] ----------------
__global__ void fmean_dot()
{
    int b = blockIdx.y;
    int m = blockIdx.x * 256 + threadIdx.x;
    __shared__ float su[NN];
    const float* Zb = g_Z[b];
    for (int n = threadIdx.x; n < NN; n += 256) su[n] = Zb[(long)n * LDZ + NN];
    __syncthreads();
    float a0 = 0.f, a1 = 0.f, a2 = 0.f, a3 = 0.f;
    #pragma unroll 4
    for (int n = 0; n < NN; n += 4) {
        a0 += Zb[(long)n * LDZ + m]       * su[n];
        a1 += Zb[(long)(n + 1) * LDZ + m] * su[n + 1];
        a2 += Zb[(long)(n + 2) * LDZ + m] * su[n + 2];
        a3 += Zb[(long)(n + 3) * LDZ + m] * su[n + 3];
    }
    g_Fp[b][m] = (a0 + a1) + (a2 + a3);
}

__global__ void fmean_comb(float* __restrict__ out)
{
    int m = blockIdx.x * 256 + threadIdx.x;
    if (m >= NN) return;
    float f0 = g_Fp[0][m], f1 = g_Fp[1][m], f2 = g_Fp[2][m], f3 = g_Fp[3][m];
    #pragma unroll
    for (int q = 0; q < LLt; q++) {
        float v = f0 * g_sm.G[0][q] + f1 * g_sm.G[1][q]
                + f2 * g_sm.G[2][q] + f3 * g_sm.G[3][q];
        out[(long)q * NN + m] = v;                                  // fmean (N_*l, 1)
        out[4096L + 2L * 16777216L + (long)m * 4 + q] = v;          // fmean.reshape(l,N_).T
    }
}

// ---------------- fvar assembly ----------------
__global__ void fvar_kernel(float* __restrict__ out)
{
    int idx = blockIdx.x * 256 + threadIdx.x;   // 262144 threads
    int a  = idx >> 8;
    int b4 = idx & 255;
    long vi = (long)a * 256 + b4;
    float4 vt = reinterpret_cast<const float4*>(g_Ctt)[vi];
    float4 w0 = reinterpret_cast<const float4*>(g_W[0])[vi];
    float4 w1 = reinterpret_cast<const float4*>(g_W[1])[vi];
    float4 w2 = reinterpret_cast<const float4*>(g_W[2])[vi];
    float4 w3 = reinterpret_cast<const float4*>(g_W[3])[vi];
    float4* fv = reinterpret_cast<float4*>(out + 4096);
    #pragma unroll
    for (int q = 0; q < 4; q++) {
        #pragma unroll
        for (int r = 0; r < 4; r++) {
            float cb = g_sm.B[q][r];
            float c0 = g_sm.G[0][q] * g_sm.G[0][r];
            float c1 = g_sm.G[1][q] * g_sm.G[1][r];
            float c2 = g_sm.G[2][q] * g_sm.G[2][r];
            float c3 = g_sm.G[3][q] * g_sm.G[3][r];
            float4 v;
            v.x = cb * vt.x - c0 * w0.x - c1 * w1.x - c2 * w2.x - c3 * w3.x;
            v.y = cb * vt.y - c0 * w0.y - c1 * w1.y - c2 * w2.y - c3 * w3.y;
            v.z = cb * vt.z - c0 * w0.z - c1 * w1.z - c2 * w2.z - c3 * w3.z;
            v.w = cb * vt.w - c0 * w0.w - c1 * w1.w - c2 * w2.w - c3 * w3.w;
            fv[(long)(q * NN + a) * 1024 + r * 256 + b4] = v;
        }
    }
}

// ---------------- noise output ----------------
__global__ void noise_zero(float* __restrict__ out)
{
    long i = (long)blockIdx.x * 256 + threadIdx.x;   // 4194304 float4's
    float4 z = make_float4(0.f, 0.f, 0.f, 0.f);
    reinterpret_cast<float4*>(out + 4096 + 16777216L)[i] = z;
}

__global__ void noise_diag(float* __restrict__ out)
{
    int r = blockIdx.x * 256 + threadIdx.x;
    if (r >= 4096) return;
    out[4096 + 16777216L + (long)r * 4096 + r] = g_sm.dn[r >> 10];
}

// ---------------- launcher ----------------
extern "C" void kernel_launch(void* const* d_in, const int* in_sizes, int n_in,
                              void* d_out, int out_size)
{
    const float* X      = (const float*)d_in[0];
    const float* tX     = (const float*)d_in[1];
    const float* Y      = (const float*)d_in[2];
    const float* lnoise = (const float*)d_in[3];
    const float* cf     = (const float*)d_in[4];
    const float* lvar   = (const float*)d_in[5];
    const float* lls    = (const float*)d_in[6];
    float* out = (float*)d_out;
    int l = in_sizes[3];
    int rank = in_sizes[4] / l;

    float *C_, *Cx_, *Lf_, *Z_, *W_, *Ctt_;
    cudaGetSymbolAddress((void**)&C_,   g_C);
    cudaGetSymbolAddress((void**)&Cx_,  g_Cx);
    cudaGetSymbolAddress((void**)&Lf_,  g_Lf);
    cudaGetSymbolAddress((void**)&Z_,   g_Z);
    cudaGetSymbolAddress((void**)&W_,   g_W);
    cudaGetSymbolAddress((void**)&Ctt_, g_Ctt);

    small_setup<<<1, 32>>>(lnoise, cf, lvar, lls, rank);
    ytil_kernel<<<4, 256>>>(Y);

    int nb2 = (NN * NN + 255) / 256;
    rbf_kernel<<<nb2, 256>>>(X,  X,  C_,   NN, NN);
    rbf_kernel<<<nb2, 256>>>(X,  tX, Cx_,  NN, NN);
    rbf_kernel<<<nb2, 256>>>(tX, tX, Ctt_, NN, NN);

    buildA_kernel<<<dim3(nb2, 1, LLt), 256>>>();
    init_Z<<<dim3(NN, LLt), 256>>>();

    // batched blocked Cholesky of A_i = s_i*C + I (lower, in place)
    for (int k = 0; k < NSTEP; k++) {
        potf2_kernel<<<LLt, 64>>>(k);
        int mrem = NSTEP - 1 - k;
        if (mrem > 0) {
            chol_panel<<<dim3(mrem, LLt), 64>>>(k);
            int mt = (mrem * NB + 127) / 128;
            gemm128<<<dim3(mt, mt, LLt), 256>>>(
                Lf_ + (long)((k + 1) * NB) * NN + k * NB, NN, (long)NN * NN, 0,
                Lf_ + (long)((k + 1) * NB) * NN + k * NB, NN, (long)NN * NN, 1,
                Lf_ + (long)((k + 1) * NB) * NN + (k + 1) * NB, NN, (long)NN * NN,
                mrem * NB, mrem * NB, NB, -1.f, 1.f, 1, 0);
        }
    }
    // forward TRSM only: Z <- L^{-1} Z
    for (int k = 0; k < NSTEP; k++) {
        trsm_fwd_diag<<<dim3(17, LLt), 64>>>(k);
        int mrem = NSTEP - 1 - k;
        if (mrem > 0) {
            int mt = (mrem * NB + 127) / 128;
            gemm128<<<dim3(mt, 9, LLt), 256>>>(
                Lf_ + (long)((k + 1) * NB) * NN + k * NB, NN, (long)NN * NN, 0,
                Z_ + (long)(k * NB) * LDZ, LDZ, (long)NN * LDZ, 0,
                Z_ + (long)((k + 1) * NB) * LDZ, LDZ, (long)NN * LDZ,
                mrem * NB, NRHS, NB, -1.f, 1.f, 0, 0);
        }
    }
    // W_i = T_i^T T_i  (batched syrk, lower tiles + mirror)
    gemm128<<<dim3(8, 8, LLt), 256>>>(
        Z_, LDZ, (long)NN * LDZ, 1,
        Z_, LDZ, (long)NN * LDZ, 0,
        W_, NN, (long)NN * NN,
        NN, NN, NN, 1.f, 0.f, 1, 1);

    // fmean = sum_i G[i][q] * T_i^T u_i
    fmean_dot<<<dim3(4, LLt), 256>>>();
    fmean_comb<<<4, 256>>>(out);

    // fvar and noise outputs
    fvar_kernel<<<1024, 256>>>(out);
    noise_zero<<<16384, 256>>>(out);
    noise_diag<<<16, 256>>>(out);
}

// round 3
// speedup vs baseline: 1.7196x; 1.3408x over previous
#include <cuda_runtime.h>
#include <math.h>

#define NN 1024           // N = N_ = 1024 training/test points
#define LLt 4             // l = 4 tasks
#define DD 8              // input dim
#define NB 64             // factorization block size
#define NSTEP 16          // NN / NB
#define LDZ 1040          // padded leading dim for Z (1025 used cols)
#define NRHS 1025         // 1024 Cx columns + 1 ytil column

// ---------------- device scratch (static: no allocation allowed) ----------------
__device__ float g_Ctt[NN * NN];        // rbf(test_X, test_X)
__device__ float g_Lf[LLt][NN * NN];    // per-batch A_i = s_i*C + I -> L panels in-place
__device__ float g_Z[LLt][NN * LDZ];    // per-batch RHS [Cx | ytil_i] -> T_i = L_i^{-1}[Cx|u]
__device__ float g_W[LLt][NN * NN];     // W_i = T_i^T T_i
__device__ float g_Fp[LLt][NN];         // per-batch T_i^T u_i

struct Small {
    float s[LLt];          // eigenvalues of B'
    float G[LLt][LLt];     // G[i][q] = (U^T D^{-1/2} B)[i][q]
    float B[LLt][LLt];     // task_K
    float dn[LLt];         // exp(log_noise)
    float DU[LLt][LLt];    // DU[p][i] = dns[p]*U[p][i]
    float inv2ls2;         // 0.5 / ls^2
};
__device__ Small g_sm;

// ---------------- small setup: task matrix, 4x4 Jacobi eig ----------------
__global__ void small_setup(const float* __restrict__ log_noise,
                            const float* __restrict__ covar_factor,
                            const float* __restrict__ log_var,
                            const float* __restrict__ log_ls, int rank)
{
    if (threadIdx.x != 0 || blockIdx.x != 0) return;
    double dn[LLt], dns[LLt];
    for (int p = 0; p < LLt; p++) {
        dn[p]  = exp((double)log_noise[p]);
        dns[p] = exp(-0.5 * (double)log_noise[p]);
    }
    double B[LLt][LLt];
    for (int q = 0; q < LLt; q++)
        for (int r = 0; r < LLt; r++) {
            double s = 0.0;
            for (int k = 0; k < rank; k++)
                s += (double)covar_factor[q * rank + k] * (double)covar_factor[r * rank + k];
            if (q == r) s += exp((double)log_var[q]);
            B[q][r] = s;
        }
    double A[LLt][LLt], V[LLt][LLt];
    for (int q = 0; q < LLt; q++)
        for (int r = 0; r < LLt; r++) {
            A[q][r] = dns[q] * B[q][r] * dns[r];
            V[q][r] = (q == r) ? 1.0 : 0.0;
        }
    for (int sweep = 0; sweep < 40; sweep++) {
        for (int p = 0; p < LLt - 1; p++)
            for (int q = p + 1; q < LLt; q++) {
                double apq = A[p][q];
                if (fabs(apq) < 1e-300) continue;
                double theta = 0.5 * atan2(2.0 * apq, A[q][q] - A[p][p]);
                double c = cos(theta), s = sin(theta);
                for (int k = 0; k < LLt; k++) {
                    double akp = A[k][p], akq = A[k][q];
                    A[k][p] = c * akp - s * akq;
                    A[k][q] = s * akp + c * akq;
                }
                for (int k = 0; k < LLt; k++) {
                    double apk = A[p][k], aqk = A[q][k];
                    A[p][k] = c * apk - s * aqk;
                    A[q][k] = s * apk + c * aqk;
                }
                for (int k = 0; k < LLt; k++) {
                    double vkp = V[k][p], vkq = V[k][q];
                    V[k][p] = c * vkp - s * vkq;
                    V[k][q] = s * vkp + c * vkq;
                }
            }
    }
    for (int i = 0; i < LLt; i++) g_sm.s[i] = (float)A[i][i];
    for (int p = 0; p < LLt; p++)
        for (int i = 0; i < LLt; i++)
            g_sm.DU[p][i] = (float)(dns[p] * V[p][i]);
    for (int i = 0; i < LLt; i++)
        for (int q = 0; q < LLt; q++) {
            double s = 0.0;
            for (int p = 0; p < LLt; p++) s += V[p][i] * dns[p] * B[p][q];
            g_sm.G[i][q] = (float)s;
        }
    for (int q = 0; q < LLt; q++)
        for (int r = 0; r < LLt; r++) g_sm.B[q][r] = (float)B[q][r];
    for (int p = 0; p < LLt; p++) g_sm.dn[p] = (float)dn[p];
    g_sm.inv2ls2 = (float)(0.5 * exp(-2.0 * (double)log_ls[0]));
}

// ---------------- ytil written straight into Z col 1024 ----------------
__global__ void ytil_kernel(const float* __restrict__ Y)
{
    int n = blockIdx.x * 256 + threadIdx.x;
    if (n >= NN) return;
    float y0 = Y[n * 4 + 0], y1 = Y[n * 4 + 1], y2 = Y[n * 4 + 2], y3 = Y[n * 4 + 3];
    #pragma unroll
    for (int i = 0; i < LLt; i++)
        g_Z[i][(long)n * LDZ + NN] = y0 * g_sm.DU[0][i] + y1 * g_sm.DU[1][i]
                                   + y2 * g_sm.DU[2][i] + y3 * g_sm.DU[3][i];
}

// ---------------- RBF kernels fused with consumers ----------------
__global__ void rbf_AA_kernel(const float* __restrict__ X)
{
    int idx = blockIdx.x * 256 + threadIdx.x;
    int i = idx >> 10, j = idx & 1023;
    float d2 = 0.f;
    #pragma unroll
    for (int d = 0; d < DD; d++) {
        float t = X[i * DD + d] - X[j * DD + d];
        d2 += t * t;
    }
    float v = expf(-d2 * g_sm.inv2ls2);
    float diag = (i == j) ? 1.f : 0.f;
    #pragma unroll
    for (int b = 0; b < LLt; b++)
        g_Lf[b][idx] = g_sm.s[b] * v + diag;
}

__global__ void rbf_Ax_kernel(const float* __restrict__ X, const float* __restrict__ tX)
{
    int idx = blockIdx.x * 256 + threadIdx.x;
    int i = idx >> 10, j = idx & 1023;
    float d2 = 0.f;
    #pragma unroll
    for (int d = 0; d < DD; d++) {
        float t = X[i * DD + d] - tX[j * DD + d];
        d2 += t * t;
    }
    float v = expf(-d2 * g_sm.inv2ls2);
    long off = (long)i * LDZ + j;
    #pragma unroll
    for (int b = 0; b < LLt; b++)
        g_Z[b][off] = v;
}

__global__ void rbf_tt_kernel(const float* __restrict__ tX)
{
    int idx = blockIdx.x * 256 + threadIdx.x;
    int i = idx >> 10, j = idx & 1023;
    float d2 = 0.f;
    #pragma unroll
    for (int d = 0; d < DD; d++) {
        float t = tX[i * DD + d] - tX[j * DD + d];
        d2 += t * t;
    }
    g_Ctt[idx] = expf(-d2 * g_sm.inv2ls2);
}

// ---------------- fused panel step: redundant diag factor + L21 + z'_k ----------------
// grid: (mrem + 17, LLt), 64 threads. Blocks < mrem: A panel rows; rest: Z columns.
__global__ void panel_step(int k)
{
    int b = blockIdx.y;
    int t = threadIdx.x;
    int mrem = NSTEP - 1 - k;
    __shared__ float sL[64][65];
    __shared__ float sX[64][65];
    float* Lb = g_Lf[b];
    int off = k * NB;
    // load diag block A_kk (fully updated by previous steps)
    for (int r = 0; r < 64; r++) sL[r][t] = Lb[(long)(off + r) * NN + off + t];
    __syncthreads();
    // redundant in-smem potf2 (lower)
    for (int j = 0; j < 64; j++) {
        if (t == j) sL[j][j] = sqrtf(sL[j][j]);
        __syncthreads();
        float inv = 1.f / sL[j][j];
        if (t > j) sL[t][j] *= inv;
        __syncthreads();
        if (t > j) {
            float ltj = sL[t][j];
            for (int c = j + 1; c <= t; c++) sL[t][c] -= ltj * sL[c][j];
        }
        __syncthreads();
    }
    __syncthreads();

    if ((int)blockIdx.x < mrem) {
        // A panel block: L21 rows = A21 * L_kk^{-T}
        int rowbase = off + NB + blockIdx.x * 64;
        for (int r = 0; r < 64; r++) sX[r][t] = Lb[(long)(rowbase + r) * NN + off + t];
        __syncthreads();
        for (int j = 0; j < 64; j++) {
            float acc = sX[t][j];
            for (int c = 0; c < j; c++) acc -= sX[t][c] * sL[j][c];
            sX[t][j] = acc / sL[j][j];
        }
        __syncthreads();
        for (int r = 0; r < 64; r++) Lb[(long)(rowbase + r) * NN + off + t] = sX[r][t];
    } else {
        // Z block: z'_k = L_kk^{-1} Z_k for 64 columns
        int col = ((int)blockIdx.x - mrem) * 64 + t;
        float* Zb = g_Z[b];
        bool ok = col < NRHS;
        for (int r = 0; r < 64; r++) sX[r][t] = ok ? Zb[(long)(off + r) * LDZ + col] : 0.f;
        __syncthreads();
        for (int j = 0; j < 64; j++) {
            float a0 = 0.f, a1 = 0.f, a2 = 0.f, a3 = 0.f;
            int c = 0;
            for (; c + 3 < j; c += 4) {
                a0 -= sL[j][c]     * sX[c][t];
                a1 -= sL[j][c + 1] * sX[c + 1][t];
                a2 -= sL[j][c + 2] * sX[c + 2][t];
                a3 -= sL[j][c + 3] * sX[c + 3][t];
            }
            for (; c < j; c++) a0 -= sL[j][c] * sX[c][t];
            sX[j][t] = (sX[j][t] + a0 + a1 + a2 + a3) / sL[j][j];
        }
        if (ok)
            for (int r = 0; r < 64; r++) Zb[(long)(off + r) * LDZ + col] = sX[r][t];
    }
}

// ---------------- merged trailing update: A22 -= L21 L21^T  AND  Z -= L21 z'_k ----------
// grid: (mt, mt + 9, LLt), 256 threads, 128x128 tiles, K=64.
__global__ void __launch_bounds__(256, 2)
update_step(int k)
{
    int b = blockIdx.z;
    int mrem = NSTEP - 1 - k;
    int mt = (mrem * NB + 127) / 128;
    int bi = blockIdx.x, bj = blockIdx.y;
    bool isA = bj < mt;
    if (isA && bj > bi) return;          // lower tiles only for A
    int M = mrem * NB;
    int rowoff = (k + 1) * NB;
    float* Lb = g_Lf[b];
    float* Zb = g_Z[b];

    __shared__ __align__(16) float As[16][132];
    __shared__ __align__(16) float Bs[16][132];
    int tid = threadIdx.x;
    int tr = tid >> 4, tc = tid & 15;
    float acc[8][8];
    #pragma unroll
    for (int u = 0; u < 8; u++)
        #pragma unroll
        for (int v = 0; v < 8; v++) acc[u][v] = 0.f;

    int zcolbase = (bj - mt) * 128;

    for (int k0 = 0; k0 < 64; k0 += 16) {
        // A operand: L21 rows (non-transposed), lda=NN
        #pragma unroll
        for (int e = tid; e < 2048; e += 256) {
            int kk = e & 15, m = e >> 4;
            int row = bi * 128 + m;
            As[kk][m] = (row < M) ? Lb[(long)(rowoff + row) * NN + k * NB + k0 + kk] : 0.f;
        }
        if (isA) {
            // B operand: L21 transposed read
            #pragma unroll
            for (int e = tid; e < 2048; e += 256) {
                int kk = e & 15, n = e >> 4;
                int col = bj * 128 + n;
                Bs[kk][n] = (col < M) ? Lb[(long)(rowoff + col) * NN + k * NB + k0 + kk] : 0.f;
            }
        } else {
            // B operand: z'_k rows
            #pragma unroll
            for (int e = tid; e < 2048; e += 256) {
                int kk = e >> 7, n = e & 127;
                int col = zcolbase + n;
                Bs[kk][n] = (col < NRHS) ? Zb[(long)(k * NB + k0 + kk) * LDZ + col] : 0.f;
            }
        }
        __syncthreads();
        #pragma unroll
        for (int kk = 0; kk < 16; kk++) {
            float a[8], bb[8];
            *reinterpret_cast<float4*>(&a[0])  = *reinterpret_cast<float4*>(&As[kk][tr * 4]);
            *reinterpret_cast<float4*>(&a[4])  = *reinterpret_cast<float4*>(&As[kk][64 + tr * 4]);
            *reinterpret_cast<float4*>(&bb[0]) = *reinterpret_cast<float4*>(&Bs[kk][tc * 4]);
            *reinterpret_cast<float4*>(&bb[4]) = *reinterpret_cast<float4*>(&Bs[kk][64 + tc * 4]);
            #pragma unroll
            for (int u = 0; u < 8; u++)
                #pragma unroll
                for (int v = 0; v < 8; v++)
                    acc[u][v] += a[u] * bb[v];
        }
        __syncthreads();
    }
    #pragma unroll
    for (int u = 0; u < 8; u++) {
        int row = bi * 128 + ((u < 4) ? tr * 4 + u : 64 + tr * 4 + (u - 4));
        if (row >= M) continue;
        #pragma unroll
        for (int v = 0; v < 8; v++) {
            int n = ((v < 4) ? tc * 4 + v : 64 + tc * 4 + (v - 4));
            if (isA) {
                int col = bj * 128 + n;
                if (col < M)
                    Lb[(long)(rowoff + row) * NN + rowoff + col] -= acc[u][v];
            } else {
                int col = zcolbase + n;
                if (col < NRHS)
                    Zb[(long)(rowoff + row) * LDZ + col] -= acc[u][v];
            }
        }
    }
}

// ---------------- 128x128-tile SGEMM for W = T^T T (syrk, lower + mirror) ----------
__global__ void __launch_bounds__(256, 2)
syrk_W()
{
    int bi = blockIdx.x, bj = blockIdx.y, b = blockIdx.z;
    if (bj > bi) return;
    const float* Zb = g_Z[b];
    float* Wb = g_W[b];
    __shared__ __align__(16) float As[16][132];
    __shared__ __align__(16) float Bs[16][132];
    int tid = threadIdx.x;
    int tr = tid >> 4, tc = tid & 15;
    float acc[8][8];
    #pragma unroll
    for (int u = 0; u < 8; u++)
        #pragma unroll
        for (int v = 0; v < 8; v++) acc[u][v] = 0.f;

    for (int k0 = 0; k0 < NN; k0 += 16) {
        #pragma unroll
        for (int e = tid; e < 2048; e += 256) {
            int kk = e & 15, m = e >> 4;       // transposed read: As[k][m] = T[k0+kk][bi*128+m]
            As[kk][m] = Zb[(long)(k0 + kk) * LDZ + bi * 128 + m];
        }
        #pragma unroll
        for (int e = tid; e < 2048; e += 256) {
            int kk = e & 15, n = e >> 4;
            Bs[kk][n] = Zb[(long)(k0 + kk) * LDZ + bj * 128 + n];
        }
        __syncthreads();
        #pragma unroll
        for (int kk = 0; kk < 16; kk++) {
            float a[8], bb[8];
            *reinterpret_cast<float4*>(&a[0])  = *reinterpret_cast<float4*>(&As[kk][tr * 4]);
            *reinterpret_cast<float4*>(&a[4])  = *reinterpret_cast<float4*>(&As[kk][64 + tr * 4]);
            *reinterpret_cast<float4*>(&bb[0]) = *reinterpret_cast<float4*>(&Bs[kk][tc * 4]);
            *reinterpret_cast<float4*>(&bb[4]) = *reinterpret_cast<float4*>(&Bs[kk][64 + tc * 4]);
            #pragma unroll
            for (int u = 0; u < 8; u++)
                #pragma unroll
                for (int v = 0; v < 8; v++)
                    acc[u][v] += a[u] * bb[v];
        }
        __syncthreads();
    }
    #pragma unroll
    for (int u = 0; u < 8; u++) {
        int row = bi * 128 + ((u < 4) ? tr * 4 + u : 64 + tr * 4 + (u - 4));
        #pragma unroll
        for (int v = 0; v < 8; v++) {
            int col = bj * 128 + ((v < 4) ? tc * 4 + v : 64 + tc * 4 + (v - 4));
            float o = acc[u][v];
            Wb[(long)row * NN + col] = o;
            if (bi != bj) Wb[(long)col * NN + row] = o;
        }
    }
}

// ---------------- fmean: Fp_b[m] = sum_n T_b[n][m] * u_b[n] ----------------
__global__ void fmean_dot()
{
    int b = blockIdx.y;
    int m = blockIdx.x * 256 + threadIdx.x;
    __shared__ float su[NN];
    const float* Zb = g_Z[b];
    for (int n = threadIdx.x; n < NN; n += 256) su[n] = Zb[(long)n * LDZ + NN];
    __syncthreads();
    float a0 = 0.f, a1 = 0.f, a2 = 0.f, a3 = 0.f;
    #pragma unroll 4
    for (int n = 0; n < NN; n += 4) {
        a0 += Zb[(long)n * LDZ + m]       * su[n];
        a1 += Zb[(long)(n + 1) * LDZ + m] * su[n + 1];
        a2 += Zb[(long)(n + 2) * LDZ + m] * su[n + 2];
        a3 += Zb[(long)(n + 3) * LDZ + m] * su[n + 3];
    }
    g_Fp[b][m] = (a0 + a1) + (a2 + a3);
}

__global__ void fmean_comb(float* __restrict__ out)
{
    int m = blockIdx.x * 256 + threadIdx.x;
    if (m >= NN) return;
    float f0 = g_Fp[0][m], f1 = g_Fp[1][m], f2 = g_Fp[2][m], f3 = g_Fp[3][m];
    #pragma unroll
    for (int q = 0; q < LLt; q++) {
        float v = f0 * g_sm.G[0][q] + f1 * g_sm.G[1][q]
                + f2 * g_sm.G[2][q] + f3 * g_sm.G[3][q];
        out[(long)q * NN + m] = v;                                  // fmean (N_*l, 1)
        out[4096L + 2L * 16777216L + (long)m * 4 + q] = v;          // fmean.reshape(l,N_).T
    }
}

// ---------------- fvar assembly ----------------
__global__ void fvar_kernel(float* __restrict__ out)
{
    int idx = blockIdx.x * 256 + threadIdx.x;   // 262144 threads
    int a  = idx >> 8;
    int b4 = idx & 255;
    long vi = (long)a * 256 + b4;
    float4 vt = reinterpret_cast<const float4*>(g_Ctt)[vi];
    float4 w0 = reinterpret_cast<const float4*>(g_W[0])[vi];
    float4 w1 = reinterpret_cast<const float4*>(g_W[1])[vi];
    float4 w2 = reinterpret_cast<const float4*>(g_W[2])[vi];
    float4 w3 = reinterpret_cast<const float4*>(g_W[3])[vi];
    float4* fv = reinterpret_cast<float4*>(out + 4096);
    #pragma unroll
    for (int q = 0; q < 4; q++) {
        #pragma unroll
        for (int r = 0; r < 4; r++) {
            float cb = g_sm.B[q][r];
            float c0 = g_sm.G[0][q] * g_sm.G[0][r];
            float c1 = g_sm.G[1][q] * g_sm.G[1][r];
            float c2 = g_sm.G[2][q] * g_sm.G[2][r];
            float c3 = g_sm.G[3][q] * g_sm.G[3][r];
            float4 v;
            v.x = cb * vt.x - c0 * w0.x - c1 * w1.x - c2 * w2.x - c3 * w3.x;
            v.y = cb * vt.y - c0 * w0.y - c1 * w1.y - c2 * w2.y - c3 * w3.y;
            v.z = cb * vt.z - c0 * w0.z - c1 * w1.z - c2 * w2.z - c3 * w3.z;
            v.w = cb * vt.w - c0 * w0.w - c1 * w1.w - c2 * w2.w - c3 * w3.w;
            fv[(long)(q * NN + a) * 1024 + r * 256 + b4] = v;
        }
    }
}

// ---------------- noise output ----------------
__global__ void noise_zero(float* __restrict__ out)
{
    long i = (long)blockIdx.x * 256 + threadIdx.x;   // 4194304 float4's
    float4 z = make_float4(0.f, 0.f, 0.f, 0.f);
    reinterpret_cast<float4*>(out + 4096 + 16777216L)[i] = z;
}

__global__ void noise_diag(float* __restrict__ out)
{
    int r = blockIdx.x * 256 + threadIdx.x;
    if (r >= 4096) return;
    out[4096 + 16777216L + (long)r * 4096 + r] = g_sm.dn[r >> 10];
}

// ---------------- launcher ----------------
extern "C" void kernel_launch(void* const* d_in, const int* in_sizes, int n_in,
                              void* d_out, int out_size)
{
    const float* X      = (const float*)d_in[0];
    const float* tX     = (const float*)d_in[1];
    const float* Y      = (const float*)d_in[2];
    const float* lnoise = (const float*)d_in[3];
    const float* cf     = (const float*)d_in[4];
    const float* lvar   = (const float*)d_in[5];
    const float* lls    = (const float*)d_in[6];
    float* out = (float*)d_out;
    int l = in_sizes[3];
    int rank = in_sizes[4] / l;
    (void)l;

    small_setup<<<1, 32>>>(lnoise, cf, lvar, lls, rank);

    int nb2 = (NN * NN) / 256;
    rbf_AA_kernel<<<nb2, 256>>>(X);
    rbf_Ax_kernel<<<nb2, 256>>>(X, tX);
    rbf_tt_kernel<<<nb2, 256>>>(tX);
    ytil_kernel<<<4, 256>>>(Y);

    // fused Cholesky + forward-solve sweep
    for (int k = 0; k < NSTEP; k++) {
        int mrem = NSTEP - 1 - k;
        panel_step<<<dim3(mrem + 17, LLt), 64>>>(k);
        if (mrem > 0) {
            int mt = (mrem * NB + 127) / 128;
            update_step<<<dim3(mt, mt + 9, LLt), 256>>>(k);
        }
    }

    // W_i = T_i^T T_i  (batched syrk, lower tiles + mirror)
    syrk_W<<<dim3(8, 8, LLt), 256>>>();

    // fmean = sum_i G[i][q] * T_i^T u_i
    fmean_dot<<<dim3(4, LLt), 256>>>();
    fmean_comb<<<4, 256>>>(out);

    // fvar and noise outputs
    fvar_kernel<<<1024, 256>>>(out);
    noise_zero<<<16384, 256>>>(out);
    noise_diag<<<16, 256>>>(out);
}